// round 2
// baseline (speedup 1.0000x reference)
#include <cuda_runtime.h>

// ---------------- problem constants ----------------
#define BB    32
#define HH    112
#define WW    112
#define CC    96
#define NHEAD 3
#define WSZ   7
#define SH    3
#define HIDD  384
#define NTOK  49          // WS*WS
#define HDIM  32          // C/NH
#define LTOT  (HH*WW)     // 12544
#define NWIMG 256         // windows per image (16*16)
#define NWTOT (BB*NWIMG)  // 8192

#define STR   97          // smem row stride for 96-wide rows (bank-conflict-free for row-stride access)

// ---------------- device scratch (no runtime allocation allowed) ----------------
__device__ float g_qkv_wT[96*288];                 // [k][j]  j = s*96 + head*32 + d
__device__ float g_proj_wT[96*96];                 // [j][c]
__device__ float g_fc1_wT[96*384];                 // [k][j]
__device__ float g_fc2_wT[384*96];                 // [h][c]
__device__ float g_comb[NWIMG*NHEAD*NTOK*NTOK];    // rel-bias + attn-mask, fused
__device__ float g_x1[(size_t)BB*LTOT*CC];         // x + attn_out (residual 1), 154 MB

// ---------------- prep: weight transposes ----------------
__global__ void prep_weights(const float* __restrict__ qkv_w, const float* __restrict__ proj_w,
                             const float* __restrict__ fc1_w, const float* __restrict__ fc2_w) {
    int i = blockIdx.x * blockDim.x + threadIdx.x;
    if (i < 96*288) { int j = i / 96, k = i % 96; g_qkv_wT[k*288 + j] = qkv_w[j*96 + k]; }
    if (i < 96*96)  { int c = i / 96, j = i % 96; g_proj_wT[j*96 + c] = proj_w[c*96 + j]; }
    if (i < 384*96) { int j = i / 96, k = i % 96; g_fc1_wT[k*384 + j] = fc1_w[j*96 + k]; }
    if (i < 96*384) { int c = i / 384, h = i % 384; g_fc2_wT[h*96 + c] = fc2_w[c*384 + h]; }
}

// ---------------- prep: fused (rel bias + shift mask) ----------------
__global__ void prep_comb(const float* __restrict__ mask, const int* __restrict__ relidx,
                          const float* __restrict__ table) {
    int i = blockIdx.x * blockDim.x + threadIdx.x;
    const int total = NWIMG*NHEAD*NTOK*NTOK;
    if (i >= total) return;
    int m = i % NTOK; int t = i / NTOK;
    int r = t % NTOK; t /= NTOK;
    int h = t % NHEAD; int w = t / NHEAD;
    g_comb[i] = table[relidx[r*NTOK + m]*NHEAD + h] + mask[(w*NTOK + r)*NTOK + m];
}

// ---------------- per-window attention megakernel ----------------
// 1 block = 1 window, 384 threads (12 warps).
// smem: xs(LN, reused as AV out) | sh(shortcut) | q | k | v | attn logits | weight tile
__global__ __launch_bounds__(384) void attn_kernel(
    const float* __restrict__ x,
    const float* __restrict__ n1g, const float* __restrict__ n1b,
    const float* __restrict__ qkv_b, const float* __restrict__ proj_b) {

    extern __shared__ float sm[];
    float* xs  = sm;                    // 49*STR (LN values; later AV output)
    float* sh  = xs  + 49*STR;          // 49*STR shortcut
    float* qs  = sh  + 49*STR;
    float* ks  = qs  + 49*STR;
    float* vs  = ks  + 49*STR;
    float* at  = vs  + 49*STR;          // 3*49*49 logits
    float* wsm = at  + 3*49*49;         // 96*96 weight staging

    const int tid  = threadIdx.x;
    const int lane = tid & 31, wid = tid >> 5;
    const int win  = blockIdx.x;
    const int b    = win >> 8, widx = win & 255;
    const int wh   = widx >> 4, wwp = widx & 15;

    // --- 1) gather (cyclic shift + window partition) + LayerNorm1 ---
    for (int t = wid; t < NTOK; t += 12) {
        int r = t / WSZ, c7 = t % WSZ;
        int hh = (wh*WSZ + r  + SH) % HH;
        int wp = (wwp*WSZ + c7 + SH) % WW;
        const float* xp = x + ((size_t)b*LTOT + hh*WW + wp)*CC;
        float v0 = xp[lane], v1 = xp[lane+32], v2 = xp[lane+64];
        float s = v0+v1+v2, ss = v0*v0 + v1*v1 + v2*v2;
        #pragma unroll
        for (int o = 16; o; o >>= 1) {
            s  += __shfl_xor_sync(0xffffffffu, s,  o);
            ss += __shfl_xor_sync(0xffffffffu, ss, o);
        }
        float mean = s * (1.f/96.f);
        float var  = ss * (1.f/96.f) - mean*mean;
        float rstd = rsqrtf(var + 1e-5f);
        sh[t*STR + lane]    = v0; sh[t*STR + lane+32] = v1; sh[t*STR + lane+64] = v2;
        xs[t*STR + lane]    = (v0-mean)*rstd*n1g[lane]    + n1b[lane];
        xs[t*STR + lane+32] = (v1-mean)*rstd*n1g[lane+32] + n1b[lane+32];
        xs[t*STR + lane+64] = (v2-mean)*rstd*n1g[lane+64] + n1b[lane+64];
    }
    __syncthreads();

    const int jc  = tid % 96;   // output column within 96
    const int grp = tid / 96;   // token group 0..3

    // --- 2) QKV GEMM: 49x96 @ 96x288 (3 chunks of 96 columns, weights staged in smem) ---
    for (int s3 = 0; s3 < 3; s3++) {
        for (int i = tid; i < 96*96; i += 384)
            wsm[i] = g_qkv_wT[(i/96)*288 + s3*96 + (i%96)];
        __syncthreads();
        float acc[13];
        float bias = qkv_b[s3*96 + jc];
        #pragma unroll
        for (int ii = 0; ii < 13; ii++) acc[ii] = bias;
        for (int k = 0; k < 96; k++) {
            float w = wsm[k*96 + jc];
            #pragma unroll
            for (int ii = 0; ii < 13; ii++)
                acc[ii] += xs[(grp + 4*ii)*STR + k] * w;   // overrun reads (n up to 51) stay inside smem alloc
        }
        float* dst = (s3 == 0) ? qs : (s3 == 1) ? ks : vs;
        float scale = (s3 == 0) ? 0.17677669529663687f : 1.f;  // HD^-0.5 applied to q
        #pragma unroll
        for (int ii = 0; ii < 13; ii++) {
            int n = grp + 4*ii;
            if (n < NTOK) dst[n*STR + jc] = acc[ii] * scale;
        }
        __syncthreads();
    }

    // --- 3) logits: q . k  + (rel bias + mask) ---
    for (int o = tid; o < 3*NTOK*NTOK; o += 384) {
        int h = o / (NTOK*NTOK); int rm = o % (NTOK*NTOK);
        int r = rm / NTOK, m = rm % NTOK;
        const float* qp = qs + r*STR + h*HDIM;
        const float* kp = ks + m*STR + h*HDIM;
        float a = 0.f;
        #pragma unroll
        for (int d = 0; d < HDIM; d++) a += qp[d] * kp[d];
        at[o] = a + g_comb[((widx*NHEAD + h)*NTOK + r)*NTOK + m];
    }
    __syncthreads();

    // --- 4) softmax over each of 147 rows of length 49 (1 warp per row) ---
    for (int row = wid; row < NHEAD*NTOK; row += 12) {
        float* p = at + row*NTOK;
        float e0 = p[lane];
        float e1 = (lane < 17) ? p[lane+32] : -1e30f;
        float mx = fmaxf(e0, e1);
        #pragma unroll
        for (int o = 16; o; o >>= 1) mx = fmaxf(mx, __shfl_xor_sync(0xffffffffu, mx, o));
        float y0 = __expf(e0 - mx);
        float y1 = (lane < 17) ? __expf(e1 - mx) : 0.f;
        float sum = y0 + y1;
        #pragma unroll
        for (int o = 16; o; o >>= 1) sum += __shfl_xor_sync(0xffffffffu, sum, o);
        float inv = 1.f / sum;
        p[lane] = y0 * inv;
        if (lane < 17) p[lane+32] = y1 * inv;
    }
    __syncthreads();

    // --- 5) AV: (49x49)@(49x32) per head; write into xs (LN values dead) ---
    for (int o = tid; o < NTOK*96; o += 384) {
        int n = o / 96, j = o % 96, h = j / HDIM;
        const float* ap = at + h*(NTOK*NTOK) + n*NTOK;
        float a = 0.f;
        #pragma unroll
        for (int m = 0; m < NTOK; m++) a += ap[m] * vs[m*STR + j];
        xs[n*STR + j] = a;
    }
    __syncthreads();

    // --- 6) proj + shortcut + window-reverse + reverse-shift scatter ---
    for (int i = tid; i < 96*96; i += 384) wsm[i] = g_proj_wT[i];
    __syncthreads();
    {
        float acc[13];
        float bias = proj_b[jc];
        #pragma unroll
        for (int ii = 0; ii < 13; ii++) acc[ii] = bias;
        for (int k = 0; k < 96; k++) {
            float w = wsm[k*96 + jc];
            #pragma unroll
            for (int ii = 0; ii < 13; ii++)
                acc[ii] += xs[(grp + 4*ii)*STR + k] * w;
        }
        #pragma unroll
        for (int ii = 0; ii < 13; ii++) {
            int n = grp + 4*ii;
            if (n < NTOK) {
                int r = n / WSZ, c7 = n % WSZ;
                int hh = (wh*WSZ + r  + SH) % HH;
                int wp = (wwp*WSZ + c7 + SH) % WW;
                g_x1[((size_t)b*LTOT + hh*WW + wp)*CC + jc] = sh[n*STR + jc] + acc[ii];
            }
        }
    }
}

// ---------------- MLP kernel: LN2 + fc1 + GELU(erf) + fc2 + residual ----------------
// 1 block = 32 tokens, 384 threads.
__global__ __launch_bounds__(384) void mlp_kernel(
    const float* __restrict__ n2g, const float* __restrict__ n2b,
    const float* __restrict__ fc1_b, const float* __restrict__ fc2_b,
    float* __restrict__ out) {

    extern __shared__ float sm[];
    float* tl  = sm;              // 32*96  LN'd
    float* tr  = tl + 32*96;      // 32*96  residual (x1)
    float* h1  = tr + 32*96;      // 32*384 hidden (post-gelu)
    float* wsm = h1 + 32*384;     // 96*96  weight staging

    const int tid = threadIdx.x, lane = tid & 31, wid = tid >> 5;
    const size_t tok0 = (size_t)blockIdx.x * 32;

    // LN2
    for (int t = wid; t < 32; t += 12) {
        const float* xp = g_x1 + (tok0 + t)*CC;
        float v0 = xp[lane], v1 = xp[lane+32], v2 = xp[lane+64];
        float s = v0+v1+v2, ss = v0*v0 + v1*v1 + v2*v2;
        #pragma unroll
        for (int o = 16; o; o >>= 1) {
            s  += __shfl_xor_sync(0xffffffffu, s,  o);
            ss += __shfl_xor_sync(0xffffffffu, ss, o);
        }
        float mean = s * (1.f/96.f);
        float var  = ss * (1.f/96.f) - mean*mean;
        float rstd = rsqrtf(var + 1e-5f);
        tr[t*96 + lane]    = v0; tr[t*96 + lane+32] = v1; tr[t*96 + lane+64] = v2;
        tl[t*96 + lane]    = (v0-mean)*rstd*n2g[lane]    + n2b[lane];
        tl[t*96 + lane+32] = (v1-mean)*rstd*n2g[lane+32] + n2b[lane+32];
        tl[t*96 + lane+64] = (v2-mean)*rstd*n2g[lane+64] + n2b[lane+64];
    }
    __syncthreads();

    const int jc  = tid % 96;
    const int grp = tid / 96;   // 0..3, tokens n = grp + 4*ii, ii<8 -> covers 0..31

    // fc1 + exact GELU, 4 chunks of 96 output columns
    for (int jb = 0; jb < HIDD; jb += 96) {
        for (int i = tid; i < 96*96; i += 384)
            wsm[i] = g_fc1_wT[(i/96)*HIDD + jb + (i%96)];
        __syncthreads();
        float acc[8];
        float bias = fc1_b[jb + jc];
        #pragma unroll
        for (int ii = 0; ii < 8; ii++) acc[ii] = bias;
        for (int k = 0; k < 96; k++) {
            float w = wsm[k*96 + jc];
            #pragma unroll
            for (int ii = 0; ii < 8; ii++) acc[ii] += tl[(grp + 4*ii)*96 + k] * w;
        }
        #pragma unroll
        for (int ii = 0; ii < 8; ii++) {
            int n = grp + 4*ii;
            float a = acc[ii];
            h1[n*HIDD + jb + jc] = 0.5f * a * (1.f + erff(a * 0.70710678118654752f));
        }
        __syncthreads();
    }

    // fc2 + residual
    float acc[8];
    float bias = fc2_b[jc];
    #pragma unroll
    for (int ii = 0; ii < 8; ii++) acc[ii] = bias;
    for (int hb = 0; hb < HIDD; hb += 96) {
        for (int i = tid; i < 96*96; i += 384)
            wsm[i] = g_fc2_wT[hb*96 + i];
        __syncthreads();
        for (int k = 0; k < 96; k++) {
            float w = wsm[k*96 + jc];
            #pragma unroll
            for (int ii = 0; ii < 8; ii++) acc[ii] += h1[(grp + 4*ii)*HIDD + hb + k] * w;
        }
        __syncthreads();
    }
    #pragma unroll
    for (int ii = 0; ii < 8; ii++) {
        int n = grp + 4*ii;
        out[(tok0 + n)*CC + jc] = tr[n*96 + jc] + acc[ii];
    }
}

// ---------------- launch ----------------
extern "C" void kernel_launch(void* const* d_in, const int* in_sizes, int n_in,
                              void* d_out, int out_size) {
    const float* x         = (const float*)d_in[0];
    const float* attn_mask = (const float*)d_in[1];
    const int*   rel_index = (const int*)  d_in[2];
    const float* norm1_g   = (const float*)d_in[3];
    const float* norm1_b   = (const float*)d_in[4];
    const float* qkv_w     = (const float*)d_in[5];
    const float* qkv_b     = (const float*)d_in[6];
    const float* proj_w    = (const float*)d_in[7];
    const float* proj_b    = (const float*)d_in[8];
    const float* rbt       = (const float*)d_in[9];
    const float* norm2_g   = (const float*)d_in[10];
    const float* norm2_b   = (const float*)d_in[11];
    const float* fc1_w     = (const float*)d_in[12];
    const float* fc1_b     = (const float*)d_in[13];
    const float* fc2_w     = (const float*)d_in[14];
    const float* fc2_b     = (const float*)d_in[15];
    float* out = (float*)d_out;

    const int attn_smem = (5*49*STR + 3*49*49 + 96*96) * (int)sizeof(float);   // 160,736 B
    const int mlp_smem  = (32*96*2 + 32*384 + 96*96) * (int)sizeof(float);     // 110,592 B
    cudaFuncSetAttribute(attn_kernel, cudaFuncAttributeMaxDynamicSharedMemorySize, attn_smem);
    cudaFuncSetAttribute(mlp_kernel,  cudaFuncAttributeMaxDynamicSharedMemorySize, mlp_smem);

    prep_weights<<<(96*384 + 255)/256, 256>>>(qkv_w, proj_w, fc1_w, fc2_w);
    prep_comb<<<(NWIMG*NHEAD*NTOK*NTOK + 255)/256, 256>>>(attn_mask, rel_index, rbt);
    attn_kernel<<<NWTOT, 384, attn_smem>>>(x, norm1_g, norm1_b, qkv_b, proj_b);
    mlp_kernel<<<(BB*LTOT)/32, 384, mlp_smem>>>(norm2_g, norm2_b, fc1_b, fc2_b, out);
}

// round 4
// speedup vs baseline: 2.5549x; 2.5549x over previous
#include <cuda_runtime.h>
#include <cuda_bf16.h>
#include <mma.h>
using namespace nvcuda;

// ---------------- problem constants ----------------
#define LTOT   12544          // 112*112
#define M_ALL  401408         // 8192 windows * 49 tokens
#define NWIN   8192
#define MT     3136           // M_ALL / 128

// ---------------- device scratch (static, no runtime alloc) ----------------
__device__ __nv_bfloat16 g_wqkv_h[288*96], g_wqkv_l[288*96];
__device__ __nv_bfloat16 g_wproj_h[96*96], g_wproj_l[96*96];
__device__ __nv_bfloat16 g_wfc1_h[384*96], g_wfc1_l[384*96];
__device__ __nv_bfloat16 g_wfc2_h[96*384], g_wfc2_l[96*384];
__device__ float         g_comb[256*3*49*49];
__device__ __nv_bfloat16 g_xa_h[(size_t)M_ALL*96],  g_xa_l[(size_t)M_ALL*96];
__device__ __nv_bfloat16 g_qkv_h[(size_t)M_ALL*288], g_qkv_l[(size_t)M_ALL*288];
__device__ __nv_bfloat16 g_att_h[(size_t)M_ALL*96], g_att_l[(size_t)M_ALL*96];
__device__ float         g_x1[(size_t)M_ALL*96];
__device__ __nv_bfloat16 g_y_h[(size_t)M_ALL*96],  g_y_l[(size_t)M_ALL*96];
__device__ __nv_bfloat16 g_hid_h[(size_t)M_ALL*384], g_hid_l[(size_t)M_ALL*384];

__device__ __forceinline__ void splitf(float v, __nv_bfloat16& h, __nv_bfloat16& l) {
    h = __float2bfloat16(v);
    l = __float2bfloat16(v - __bfloat162float(h));
}

// ---------------- prep: weights -> split bf16 ----------------
__global__ void prep_weights(const float* __restrict__ qkv_w, const float* __restrict__ proj_w,
                             const float* __restrict__ fc1_w, const float* __restrict__ fc2_w) {
    int i = blockIdx.x * blockDim.x + threadIdx.x;
    if (i < 288*96) splitf(qkv_w[i],  g_wqkv_h[i], g_wqkv_l[i]);
    if (i < 96*96)  splitf(proj_w[i], g_wproj_h[i], g_wproj_l[i]);
    if (i < 384*96) splitf(fc1_w[i],  g_wfc1_h[i], g_wfc1_l[i]);
    if (i < 96*384) splitf(fc2_w[i],  g_wfc2_h[i], g_wfc2_l[i]);
}

// ---------------- prep: fused (rel bias + shift mask) ----------------
__global__ void prep_comb(const float* __restrict__ mask, const int* __restrict__ relidx,
                          const float* __restrict__ table) {
    int i = blockIdx.x * blockDim.x + threadIdx.x;
    if (i >= 256*3*49*49) return;
    int m = i % 49; int t = i / 49;
    int r = t % 49; t /= 49;
    int h = t % 3;  int w = t / 3;
    g_comb[i] = table[relidx[r*49 + m]*3 + h] + mask[(w*49 + r)*49 + m];
}

// ---------------- LN1 + cyclic shift + window gather -> split bf16 ----------------
__global__ __launch_bounds__(256) void ln1_gather(const float* __restrict__ x,
        const float* __restrict__ g, const float* __restrict__ bta) {
    const int tid = threadIdx.x, lane = tid & 31, wid = tid >> 5;
    const int win = blockIdx.x;
    const int b = win >> 8, widx = win & 255, wh = widx >> 4, ww = widx & 15;
    for (int t = wid; t < 49; t += 8) {
        int r = t / 7, c7 = t % 7;
        int hh = (wh*7 + r  + 3) % 112;
        int wp = (ww*7 + c7 + 3) % 112;
        const float* xp = x + ((size_t)b*LTOT + hh*112 + wp)*96;
        float v0 = xp[lane], v1 = xp[lane+32], v2 = xp[lane+64];
        float s = v0+v1+v2, ss = v0*v0 + v1*v1 + v2*v2;
        #pragma unroll
        for (int o = 16; o; o >>= 1) {
            s  += __shfl_xor_sync(0xffffffffu, s,  o);
            ss += __shfl_xor_sync(0xffffffffu, ss, o);
        }
        float mean = s*(1.f/96.f), var = ss*(1.f/96.f) - mean*mean;
        float rstd = rsqrtf(var + 1e-5f);
        size_t base = ((size_t)win*49 + t)*96;
        float w0 = (v0-mean)*rstd*g[lane]    + bta[lane];
        float w1 = (v1-mean)*rstd*g[lane+32] + bta[lane+32];
        float w2 = (v2-mean)*rstd*g[lane+64] + bta[lane+64];
        splitf(w0, g_xa_h[base+lane],    g_xa_l[base+lane]);
        splitf(w1, g_xa_h[base+lane+32], g_xa_l[base+lane+32]);
        splitf(w2, g_xa_h[base+lane+64], g_xa_l[base+lane+64]);
    }
}

// ---------------- LN2 ----------------
__global__ __launch_bounds__(256) void ln2_kernel(const float* __restrict__ g,
                                                  const float* __restrict__ bta) {
    const int tid = threadIdx.x, lane = tid & 31, wid = tid >> 5;
    const size_t tok = (size_t)blockIdx.x * 8 + wid;
    const float* xp = g_x1 + tok*96;
    float v0 = xp[lane], v1 = xp[lane+32], v2 = xp[lane+64];
    float s = v0+v1+v2, ss = v0*v0 + v1*v1 + v2*v2;
    #pragma unroll
    for (int o = 16; o; o >>= 1) {
        s  += __shfl_xor_sync(0xffffffffu, s,  o);
        ss += __shfl_xor_sync(0xffffffffu, ss, o);
    }
    float mean = s*(1.f/96.f), var = ss*(1.f/96.f) - mean*mean;
    float rstd = rsqrtf(var + 1e-5f);
    size_t base = tok*96;
    float w0 = (v0-mean)*rstd*g[lane]    + bta[lane];
    float w1 = (v1-mean)*rstd*g[lane+32] + bta[lane+32];
    float w2 = (v2-mean)*rstd*g[lane+64] + bta[lane+64];
    splitf(w0, g_y_h[base+lane],    g_y_l[base+lane]);
    splitf(w1, g_y_h[base+lane+32], g_y_l[base+lane+32]);
    splitf(w2, g_y_h[base+lane+64], g_y_l[base+lane+64]);
}

// ---------------- split-bf16 3-term GEMM with fused epilogues ----------------
// C[128 x (NCH*96)] = (Ah+Al)[128 x K] @ (Bh+Bl)^T    (B rows = output features)
// smem layout (bytes): [0,512) sidx | [512,..) Ash,Asl 128x112 each | [57856,..) Bsh,Bsl 96x112; Cs f32 128x100 overlays B
enum { EPI_QKV = 0, EPI_PROJ = 1, EPI_FC1 = 2, EPI_FC2 = 3 };

template<int K, int NCH, int EPI>
__global__ __launch_bounds__(256) void gemm_kernel(
    const float* __restrict__ bias,
    const float* __restrict__ xres,   // PROJ: original x (residual source)
    float* __restrict__ outf)         // FC2: d_out
{
    // device-side global pointer resolution (no __device__ symbols via host args)
    const __nv_bfloat16* Ah = (EPI==EPI_QKV) ? g_xa_h : (EPI==EPI_PROJ) ? g_att_h
                            : (EPI==EPI_FC1) ? g_y_h  : g_hid_h;
    const __nv_bfloat16* Al = (EPI==EPI_QKV) ? g_xa_l : (EPI==EPI_PROJ) ? g_att_l
                            : (EPI==EPI_FC1) ? g_y_l  : g_hid_l;
    const __nv_bfloat16* Bh = (EPI==EPI_QKV) ? g_wqkv_h : (EPI==EPI_PROJ) ? g_wproj_h
                            : (EPI==EPI_FC1) ? g_wfc1_h : g_wfc2_h;
    const __nv_bfloat16* Bl = (EPI==EPI_QKV) ? g_wqkv_l : (EPI==EPI_PROJ) ? g_wproj_l
                            : (EPI==EPI_FC1) ? g_wfc1_l : g_wfc2_l;

    extern __shared__ char smem[];
    int* sidx = (int*)smem;
    __nv_bfloat16* Ash = (__nv_bfloat16*)(smem + 512);
    __nv_bfloat16* Asl = Ash + 128*112;
    __nv_bfloat16* Bsh = (__nv_bfloat16*)(smem + 57856);
    __nv_bfloat16* Bsl = Bsh + 96*112;
    float* Cs = (float*)(smem + 57856);

    const int tid = threadIdx.x, wid = tid >> 5;
    const int m0 = blockIdx.x * 128;
    const int wm = wid & 3, wn = wid >> 2;

    if (EPI == EPI_PROJ && tid < 128) {
        int r = m0 + tid;
        int win = r / 49, t = r % 49;
        int b = win >> 8, widx = win & 255;
        int rr = t / 7, cc = t % 7;
        int hh = ((widx >> 4)*7 + rr + 3) % 112;
        int wp = ((widx & 15)*7 + cc + 3) % 112;
        sidx[tid] = b*LTOT + hh*112 + wp;
    }

    for (int nc = 0; nc < NCH; nc++) {
        wmma::fragment<wmma::accumulator,16,16,16,float> acc[2][3];
        #pragma unroll
        for (int mi = 0; mi < 2; mi++)
            #pragma unroll
            for (int ni = 0; ni < 3; ni++) wmma::fill_fragment(acc[mi][ni], 0.f);

        for (int kk = 0; kk < K; kk += 96) {
            if (K > 96 || nc == 0) {
                for (int i = tid; i < 128*12; i += 256) {
                    int mr = i/12, k8 = (i%12)*8;
                    *(uint4*)(Ash + mr*112 + k8) = *(const uint4*)(Ah + (size_t)(m0+mr)*K + kk + k8);
                    *(uint4*)(Asl + mr*112 + k8) = *(const uint4*)(Al + (size_t)(m0+mr)*K + kk + k8);
                }
            }
            for (int i = tid; i < 96*12; i += 256) {
                int n = i/12, k8 = (i%12)*8;
                *(uint4*)(Bsh + n*112 + k8) = *(const uint4*)(Bh + (size_t)(nc*96+n)*K + kk + k8);
                *(uint4*)(Bsl + n*112 + k8) = *(const uint4*)(Bl + (size_t)(nc*96+n)*K + kk + k8);
            }
            __syncthreads();
            #pragma unroll
            for (int ks = 0; ks < 6; ks++) {
                wmma::fragment<wmma::matrix_a,16,16,16,__nv_bfloat16,wmma::row_major> ah[2], al[2];
                wmma::fragment<wmma::matrix_b,16,16,16,__nv_bfloat16,wmma::col_major> bh[3], bl[3];
                #pragma unroll
                for (int mi = 0; mi < 2; mi++) {
                    wmma::load_matrix_sync(ah[mi], Ash + (wm*32 + mi*16)*112 + ks*16, 112);
                    wmma::load_matrix_sync(al[mi], Asl + (wm*32 + mi*16)*112 + ks*16, 112);
                }
                #pragma unroll
                for (int ni = 0; ni < 3; ni++) {
                    wmma::load_matrix_sync(bh[ni], Bsh + (wn*48 + ni*16)*112 + ks*16, 112);
                    wmma::load_matrix_sync(bl[ni], Bsl + (wn*48 + ni*16)*112 + ks*16, 112);
                }
                #pragma unroll
                for (int mi = 0; mi < 2; mi++)
                    #pragma unroll
                    for (int ni = 0; ni < 3; ni++) {
                        wmma::mma_sync(acc[mi][ni], ah[mi], bh[ni], acc[mi][ni]);
                        wmma::mma_sync(acc[mi][ni], ah[mi], bl[ni], acc[mi][ni]);
                        wmma::mma_sync(acc[mi][ni], al[mi], bh[ni], acc[mi][ni]);
                    }
            }
            __syncthreads();
        }

        #pragma unroll
        for (int mi = 0; mi < 2; mi++)
            #pragma unroll
            for (int ni = 0; ni < 3; ni++)
                wmma::store_matrix_sync(Cs + (wm*32 + mi*16)*100 + wn*48 + ni*16,
                                        acc[mi][ni], 100, wmma::mem_row_major);
        __syncthreads();

        for (int i = tid; i < 128*48; i += 256) {
            int row = i / 48, c2 = (i % 48) * 2;
            float v0 = Cs[row*100 + c2];
            float v1 = Cs[row*100 + c2 + 1];
            if (EPI == EPI_QKV) {
                int n = nc*96 + c2;
                v0 += bias[n]; v1 += bias[n+1];
                __nv_bfloat162 h2, l2;
                splitf(v0, h2.x, l2.x); splitf(v1, h2.y, l2.y);
                size_t o = (size_t)(m0+row)*288 + n;
                *(__nv_bfloat162*)(g_qkv_h + o) = h2;
                *(__nv_bfloat162*)(g_qkv_l + o) = l2;
            } else if (EPI == EPI_PROJ) {
                v0 += bias[c2]; v1 += bias[c2+1];
                size_t o = (size_t)sidx[row]*96 + c2;
                float2 xr = *(const float2*)(xres + o);
                float2 w; w.x = xr.x + v0; w.y = xr.y + v1;
                *(float2*)(g_x1 + o) = w;
            } else if (EPI == EPI_FC1) {
                int n = nc*96 + c2;
                v0 += bias[n]; v1 += bias[n+1];
                v0 = 0.5f*v0*(1.f + erff(v0*0.70710678118654752f));
                v1 = 0.5f*v1*(1.f + erff(v1*0.70710678118654752f));
                __nv_bfloat162 h2, l2;
                splitf(v0, h2.x, l2.x); splitf(v1, h2.y, l2.y);
                size_t o = (size_t)(m0+row)*384 + n;
                *(__nv_bfloat162*)(g_hid_h + o) = h2;
                *(__nv_bfloat162*)(g_hid_l + o) = l2;
            } else { // FC2
                v0 += bias[c2]; v1 += bias[c2+1];
                size_t o = (size_t)(m0+row)*96 + c2;
                float2 xr = *(const float2*)(g_x1 + o);
                float2 w; w.x = xr.x + v0; w.y = xr.y + v1;
                *(float2*)(outf + o) = w;
            }
        }
        __syncthreads();
    }
}

// ---------------- attention core ----------------
// smem: qs,ks (hi) | vh,vl | at f32 64x68 | ph,pl 64x72 ; st overlays at
__global__ __launch_bounds__(256) void attn_kernel() {
    extern __shared__ char smc[];
    __nv_bfloat16* qs = (__nv_bfloat16*)smc;            // 64*104*2 = 13312 each
    __nv_bfloat16* ks = qs + 64*104;
    __nv_bfloat16* vh = ks + 64*104;
    __nv_bfloat16* vl = vh + 64*104;
    float*         at = (float*)(smc + 4*13312);        // 17408
    __nv_bfloat16* ph = (__nv_bfloat16*)(smc + 4*13312 + 17408);  // 9216 each
    __nv_bfloat16* pl = ph + 64*72;
    float*         st = at;

    const int tid = threadIdx.x, lane = tid & 31, wid = tid >> 5;
    const int win = blockIdx.x, widx = win & 255;
    const size_t rowbase = (size_t)win * 49;

    // load q,k (hi), v (hi+lo); zero pad rows 49..63 of all tiles
    for (int i = tid; i < 49*48; i += 256) {
        int t = i / 48, p = i % 48;
        uint4 v;
        __nv_bfloat16* dst;
        if (p < 36) {
            v = *(const uint4*)(g_qkv_h + (rowbase + t)*288 + p*8);
            dst = (p < 12) ? (qs + t*104 + p*8)
                : (p < 24) ? (ks + t*104 + (p-12)*8)
                           : (vh + t*104 + (p-24)*8);
        } else {
            v = *(const uint4*)(g_qkv_l + (rowbase + t)*288 + 192 + (p-36)*8);
            dst = vl + t*104 + (p-36)*8;
        }
        *(uint4*)dst = v;
    }
    for (int i = tid; i < 15*13; i += 256) {
        int t = 49 + i/13, p = (i%13)*8;
        uint4 z = make_uint4(0,0,0,0);
        *(uint4*)(qs + t*104 + p) = z;
        *(uint4*)(ks + t*104 + p) = z;
        *(uint4*)(vh + t*104 + p) = z;
        *(uint4*)(vl + t*104 + p) = z;
    }
    __syncthreads();

    for (int h = 0; h < 3; h++) {
        // logits = Q @ K^T (hi only)
        {
            int f = wid*2;
            int fr = f >> 2, fc0 = f & 3, fc1 = fc0 + 1;
            wmma::fragment<wmma::accumulator,16,16,16,float> c0, c1;
            wmma::fragment<wmma::matrix_a,16,16,16,__nv_bfloat16,wmma::row_major> a;
            wmma::fragment<wmma::matrix_b,16,16,16,__nv_bfloat16,wmma::col_major> b0, b1;
            wmma::fill_fragment(c0, 0.f); wmma::fill_fragment(c1, 0.f);
            #pragma unroll
            for (int kt = 0; kt < 2; kt++) {
                wmma::load_matrix_sync(a,  qs + (fr*16)*104  + h*32 + kt*16, 104);
                wmma::load_matrix_sync(b0, ks + (fc0*16)*104 + h*32 + kt*16, 104);
                wmma::load_matrix_sync(b1, ks + (fc1*16)*104 + h*32 + kt*16, 104);
                wmma::mma_sync(c0, a, b0, c0);
                wmma::mma_sync(c1, a, b1, c1);
            }
            wmma::store_matrix_sync(at + (fr*16)*68 + fc0*16, c0, 68, wmma::mem_row_major);
            wmma::store_matrix_sync(at + (fr*16)*68 + fc1*16, c1, 68, wmma::mem_row_major);
        }
        __syncthreads();
        // scale + bias/mask + softmax -> split probs
        for (int row = wid; row < 49; row += 8) {
            const float s = 0.17677669529663687f;
            float* p = at + row*68;
            const float* cb = g_comb + (((size_t)widx*3 + h)*49 + row)*49;
            float e0 = p[lane]*s + cb[lane];
            float e1 = (lane < 17) ? p[lane+32]*s + cb[lane+32] : -1e30f;
            float mx = fmaxf(e0, e1);
            #pragma unroll
            for (int o = 16; o; o >>= 1) mx = fmaxf(mx, __shfl_xor_sync(0xffffffffu, mx, o));
            float y0 = __expf(e0 - mx);
            float y1 = (lane < 17) ? __expf(e1 - mx) : 0.f;
            float sum = y0 + y1;
            #pragma unroll
            for (int o = 16; o; o >>= 1) sum += __shfl_xor_sync(0xffffffffu, sum, o);
            float inv = 1.f / sum;
            float p0 = y0 * inv, p1 = y1 * inv;
            __nv_bfloat16 hh0, ll0, hh1, ll1;
            splitf(p0, hh0, ll0); splitf(p1, hh1, ll1);
            ph[row*72 + lane]      = hh0; pl[row*72 + lane]      = ll0;
            ph[row*72 + lane + 32] = hh1; pl[row*72 + lane + 32] = ll1;
        }
        __syncthreads();
        // out = P @ V  (3-term split)
        {
            int fr = wid >> 1, fc = wid & 1;
            wmma::fragment<wmma::accumulator,16,16,16,float> c;
            wmma::fragment<wmma::matrix_a,16,16,16,__nv_bfloat16,wmma::row_major> pa, pb2;
            wmma::fragment<wmma::matrix_b,16,16,16,__nv_bfloat16,wmma::row_major> vb, vb2;
            wmma::fill_fragment(c, 0.f);
            #pragma unroll
            for (int kt = 0; kt < 4; kt++) {
                wmma::load_matrix_sync(pa,  ph + (fr*16)*72 + kt*16, 72);
                wmma::load_matrix_sync(pb2, pl + (fr*16)*72 + kt*16, 72);
                wmma::load_matrix_sync(vb,  vh + (kt*16)*104 + h*32 + fc*16, 104);
                wmma::load_matrix_sync(vb2, vl + (kt*16)*104 + h*32 + fc*16, 104);
                wmma::mma_sync(c, pa, vb, c);
                wmma::mma_sync(c, pa, vb2, c);
                wmma::mma_sync(c, pb2, vb, c);
            }
            wmma::store_matrix_sync(st + (fr*16)*36 + fc*16, c, 36, wmma::mem_row_major);
        }
        __syncthreads();
        // write this head's 49x32 (split)
        for (int i = tid; i < 49*16; i += 256) {
            int t = i / 16, d2 = (i % 16) * 2;
            float v0 = st[t*36 + d2], v1 = st[t*36 + d2 + 1];
            __nv_bfloat162 h2, l2;
            splitf(v0, h2.x, l2.x); splitf(v1, h2.y, l2.y);
            size_t o = (rowbase + t)*96 + h*32 + d2;
            *(__nv_bfloat162*)(g_att_h + o) = h2;
            *(__nv_bfloat162*)(g_att_l + o) = l2;
        }
        __syncthreads();
    }
}

// ---------------- launch ----------------
extern "C" void kernel_launch(void* const* d_in, const int* in_sizes, int n_in,
                              void* d_out, int out_size) {
    const float* x         = (const float*)d_in[0];
    const float* attn_mask = (const float*)d_in[1];
    const int*   rel_index = (const int*)  d_in[2];
    const float* norm1_g   = (const float*)d_in[3];
    const float* norm1_b   = (const float*)d_in[4];
    const float* qkv_w     = (const float*)d_in[5];
    const float* qkv_b     = (const float*)d_in[6];
    const float* proj_w    = (const float*)d_in[7];
    const float* proj_b    = (const float*)d_in[8];
    const float* rbt       = (const float*)d_in[9];
    const float* norm2_g   = (const float*)d_in[10];
    const float* norm2_b   = (const float*)d_in[11];
    const float* fc1_w     = (const float*)d_in[12];
    const float* fc1_b     = (const float*)d_in[13];
    const float* fc2_w     = (const float*)d_in[14];
    const float* fc2_b     = (const float*)d_in[15];
    float* out = (float*)d_out;

    const int gemm_smem = 57856 + 51200;           // 109056
    const int attn_smem = 4*13312 + 17408 + 2*9216; // 89088
    cudaFuncSetAttribute(gemm_kernel<96,3,EPI_QKV>,  cudaFuncAttributeMaxDynamicSharedMemorySize, gemm_smem);
    cudaFuncSetAttribute(gemm_kernel<96,1,EPI_PROJ>, cudaFuncAttributeMaxDynamicSharedMemorySize, gemm_smem);
    cudaFuncSetAttribute(gemm_kernel<96,4,EPI_FC1>,  cudaFuncAttributeMaxDynamicSharedMemorySize, gemm_smem);
    cudaFuncSetAttribute(gemm_kernel<384,1,EPI_FC2>, cudaFuncAttributeMaxDynamicSharedMemorySize, gemm_smem);
    cudaFuncSetAttribute(attn_kernel, cudaFuncAttributeMaxDynamicSharedMemorySize, attn_smem);

    prep_weights<<<(36864 + 255)/256, 256>>>(qkv_w, proj_w, fc1_w, fc2_w);
    prep_comb<<<(256*3*49*49 + 255)/256, 256>>>(attn_mask, rel_index, rbt);
    ln1_gather<<<NWIN, 256>>>(x, norm1_g, norm1_b);
    gemm_kernel<96,3,EPI_QKV><<<MT, 256, gemm_smem>>>(qkv_b, nullptr, nullptr);
    attn_kernel<<<NWIN, 256, attn_smem>>>();
    gemm_kernel<96,1,EPI_PROJ><<<MT, 256, gemm_smem>>>(proj_b, x, nullptr);
    ln2_kernel<<<M_ALL/8, 256>>>(norm2_g, norm2_b);
    gemm_kernel<96,4,EPI_FC1><<<MT, 256, gemm_smem>>>(fc1_b, nullptr, nullptr);
    gemm_kernel<384,1,EPI_FC2><<<MT, 256, gemm_smem>>>(fc2_b, nullptr, out);
}

// round 5
// speedup vs baseline: 3.4533x; 1.3516x over previous
#include <cuda_runtime.h>
#include <cuda_bf16.h>
#include <mma.h>
using namespace nvcuda;

// ---------------- problem constants ----------------
#define LTOT   12544          // 112*112
#define M_ALL  401408         // 8192 windows * 49 tokens
#define NWIN   8192
#define MT     3136           // M_ALL / 128

// ---------------- device scratch (static, no runtime alloc) ----------------
__device__ __nv_bfloat16 g_wqkv[288*96];
__device__ __nv_bfloat16 g_wproj[96*96];
__device__ __nv_bfloat16 g_wfc1[384*96];
__device__ __nv_bfloat16 g_wfc2[96*384];
__device__ float         g_comb[256*3*49*49];
__device__ __nv_bfloat16 g_xa [(size_t)M_ALL*96];
__device__ __nv_bfloat16 g_qkv[(size_t)M_ALL*288];
__device__ __nv_bfloat16 g_att[(size_t)M_ALL*96];
__device__ float         g_x1 [(size_t)M_ALL*96];
__device__ __nv_bfloat16 g_y  [(size_t)M_ALL*96];
__device__ __nv_bfloat16 g_hid[(size_t)M_ALL*384];

// ---------------- prep: weights -> bf16 ----------------
__global__ void prep_weights(const float* __restrict__ qkv_w, const float* __restrict__ proj_w,
                             const float* __restrict__ fc1_w, const float* __restrict__ fc2_w) {
    int i = blockIdx.x * blockDim.x + threadIdx.x;
    if (i < 288*96) g_wqkv[i] = __float2bfloat16(qkv_w[i]);
    if (i < 96*96)  g_wproj[i] = __float2bfloat16(proj_w[i]);
    if (i < 384*96) g_wfc1[i]  = __float2bfloat16(fc1_w[i]);
    if (i < 96*384) g_wfc2[i]  = __float2bfloat16(fc2_w[i]);
}

// ---------------- prep: fused (rel bias + shift mask) ----------------
__global__ void prep_comb(const float* __restrict__ mask, const int* __restrict__ relidx,
                          const float* __restrict__ table) {
    int i = blockIdx.x * blockDim.x + threadIdx.x;
    if (i >= 256*3*49*49) return;
    int m = i % 49; int t = i / 49;
    int r = t % 49; t /= 49;
    int h = t % 3;  int w = t / 3;
    g_comb[i] = table[relidx[r*49 + m]*3 + h] + mask[(w*49 + r)*49 + m];
}

// ---------------- LN1 + cyclic shift + window gather -> bf16 ----------------
__global__ __launch_bounds__(256) void ln1_gather(const float* __restrict__ x,
        const float* __restrict__ g, const float* __restrict__ bta) {
    const int tid = threadIdx.x, lane = tid & 31, wid = tid >> 5;
    const int win = blockIdx.x;
    const int b = win >> 8, widx = win & 255, wh = widx >> 4, ww = widx & 15;
    for (int t = wid; t < 49; t += 8) {
        int r = t / 7, c7 = t % 7;
        int hh = (wh*7 + r  + 3) % 112;
        int wp = (ww*7 + c7 + 3) % 112;
        const float* xp = x + ((size_t)b*LTOT + hh*112 + wp)*96;
        float v0 = xp[lane], v1 = xp[lane+32], v2 = xp[lane+64];
        float s = v0+v1+v2, ss = v0*v0 + v1*v1 + v2*v2;
        #pragma unroll
        for (int o = 16; o; o >>= 1) {
            s  += __shfl_xor_sync(0xffffffffu, s,  o);
            ss += __shfl_xor_sync(0xffffffffu, ss, o);
        }
        float mean = s*(1.f/96.f), var = ss*(1.f/96.f) - mean*mean;
        float rstd = rsqrtf(var + 1e-5f);
        size_t base = ((size_t)win*49 + t)*96;
        g_xa[base+lane]    = __float2bfloat16((v0-mean)*rstd*g[lane]    + bta[lane]);
        g_xa[base+lane+32] = __float2bfloat16((v1-mean)*rstd*g[lane+32] + bta[lane+32]);
        g_xa[base+lane+64] = __float2bfloat16((v2-mean)*rstd*g[lane+64] + bta[lane+64]);
    }
}

// ---------------- LN2 ----------------
__global__ __launch_bounds__(256) void ln2_kernel(const float* __restrict__ g,
                                                  const float* __restrict__ bta) {
    const int tid = threadIdx.x, lane = tid & 31, wid = tid >> 5;
    const size_t tok = (size_t)blockIdx.x * 8 + wid;
    const float* xp = g_x1 + tok*96;
    float v0 = xp[lane], v1 = xp[lane+32], v2 = xp[lane+64];
    float s = v0+v1+v2, ss = v0*v0 + v1*v1 + v2*v2;
    #pragma unroll
    for (int o = 16; o; o >>= 1) {
        s  += __shfl_xor_sync(0xffffffffu, s,  o);
        ss += __shfl_xor_sync(0xffffffffu, ss, o);
    }
    float mean = s*(1.f/96.f), var = ss*(1.f/96.f) - mean*mean;
    float rstd = rsqrtf(var + 1e-5f);
    size_t base = tok*96;
    g_y[base+lane]    = __float2bfloat16((v0-mean)*rstd*g[lane]    + bta[lane]);
    g_y[base+lane+32] = __float2bfloat16((v1-mean)*rstd*g[lane+32] + bta[lane+32]);
    g_y[base+lane+64] = __float2bfloat16((v2-mean)*rstd*g[lane+64] + bta[lane+64]);
}

// ---------------- bf16 GEMM with fused epilogues ----------------
// C[128 x (NCH*96)] = A[128 x K] @ B^T    (B rows = output features)
// smem bytes: [0,512) sidx | [512,..) As 128x112 | [29184,..) Bs 96x112; Cs f32 128x100 overlays Bs
enum { EPI_QKV = 0, EPI_PROJ = 1, EPI_FC1 = 2, EPI_FC2 = 3 };

template<int K, int NCH, int EPI>
__global__ __launch_bounds__(256) void gemm_kernel(
    const float* __restrict__ bias,
    const float* __restrict__ xres,   // PROJ: original x (residual source)
    float* __restrict__ outf)         // FC2: d_out
{
    const __nv_bfloat16* A = (EPI==EPI_QKV) ? g_xa : (EPI==EPI_PROJ) ? g_att
                           : (EPI==EPI_FC1) ? g_y  : g_hid;
    const __nv_bfloat16* B = (EPI==EPI_QKV) ? g_wqkv : (EPI==EPI_PROJ) ? g_wproj
                           : (EPI==EPI_FC1) ? g_wfc1 : g_wfc2;

    extern __shared__ char smem[];
    int* sidx = (int*)smem;
    __nv_bfloat16* As = (__nv_bfloat16*)(smem + 512);
    __nv_bfloat16* Bs = (__nv_bfloat16*)(smem + 29184);
    float* Cs = (float*)(smem + 29184);

    const int tid = threadIdx.x, wid = tid >> 5;
    const int m0 = blockIdx.x * 128;
    const int wm = wid & 3, wn = wid >> 2;

    if (EPI == EPI_PROJ && tid < 128) {
        int r = m0 + tid;
        int win = r / 49, t = r % 49;
        int b = win >> 8, widx = win & 255;
        int rr = t / 7, cc = t % 7;
        int hh = ((widx >> 4)*7 + rr + 3) % 112;
        int wp = ((widx & 15)*7 + cc + 3) % 112;
        sidx[tid] = b*LTOT + hh*112 + wp;
    }

    for (int nc = 0; nc < NCH; nc++) {
        wmma::fragment<wmma::accumulator,16,16,16,float> acc[2][3];
        #pragma unroll
        for (int mi = 0; mi < 2; mi++)
            #pragma unroll
            for (int ni = 0; ni < 3; ni++) wmma::fill_fragment(acc[mi][ni], 0.f);

        for (int kk = 0; kk < K; kk += 96) {
            if (K > 96 || nc == 0) {
                for (int i = tid; i < 128*12; i += 256) {
                    int mr = i/12, k8 = (i%12)*8;
                    *(uint4*)(As + mr*112 + k8) = *(const uint4*)(A + (size_t)(m0+mr)*K + kk + k8);
                }
            }
            for (int i = tid; i < 96*12; i += 256) {
                int n = i/12, k8 = (i%12)*8;
                *(uint4*)(Bs + n*112 + k8) = *(const uint4*)(B + (size_t)(nc*96+n)*K + kk + k8);
            }
            __syncthreads();
            #pragma unroll
            for (int ks = 0; ks < 6; ks++) {
                wmma::fragment<wmma::matrix_a,16,16,16,__nv_bfloat16,wmma::row_major> af[2];
                wmma::fragment<wmma::matrix_b,16,16,16,__nv_bfloat16,wmma::col_major> bf[3];
                #pragma unroll
                for (int mi = 0; mi < 2; mi++)
                    wmma::load_matrix_sync(af[mi], As + (wm*32 + mi*16)*112 + ks*16, 112);
                #pragma unroll
                for (int ni = 0; ni < 3; ni++)
                    wmma::load_matrix_sync(bf[ni], Bs + (wn*48 + ni*16)*112 + ks*16, 112);
                #pragma unroll
                for (int mi = 0; mi < 2; mi++)
                    #pragma unroll
                    for (int ni = 0; ni < 3; ni++)
                        wmma::mma_sync(acc[mi][ni], af[mi], bf[ni], acc[mi][ni]);
            }
            __syncthreads();
        }

        #pragma unroll
        for (int mi = 0; mi < 2; mi++)
            #pragma unroll
            for (int ni = 0; ni < 3; ni++)
                wmma::store_matrix_sync(Cs + (wm*32 + mi*16)*100 + wn*48 + ni*16,
                                        acc[mi][ni], 100, wmma::mem_row_major);
        __syncthreads();

        for (int i = tid; i < 128*48; i += 256) {
            int row = i / 48, c2 = (i % 48) * 2;
            float v0 = Cs[row*100 + c2];
            float v1 = Cs[row*100 + c2 + 1];
            if (EPI == EPI_QKV) {
                int n = nc*96 + c2;
                v0 += bias[n]; v1 += bias[n+1];
                __nv_bfloat162 h2;
                h2.x = __float2bfloat16(v0); h2.y = __float2bfloat16(v1);
                *(__nv_bfloat162*)(g_qkv + (size_t)(m0+row)*288 + n) = h2;
            } else if (EPI == EPI_PROJ) {
                v0 += bias[c2]; v1 += bias[c2+1];
                size_t o = (size_t)sidx[row]*96 + c2;
                float2 xr = *(const float2*)(xres + o);
                float2 w; w.x = xr.x + v0; w.y = xr.y + v1;
                *(float2*)(g_x1 + o) = w;
            } else if (EPI == EPI_FC1) {
                int n = nc*96 + c2;
                v0 += bias[n]; v1 += bias[n+1];
                v0 = 0.5f*v0*(1.f + erff(v0*0.70710678118654752f));
                v1 = 0.5f*v1*(1.f + erff(v1*0.70710678118654752f));
                __nv_bfloat162 h2;
                h2.x = __float2bfloat16(v0); h2.y = __float2bfloat16(v1);
                *(__nv_bfloat162*)(g_hid + (size_t)(m0+row)*384 + n) = h2;
            } else { // FC2
                v0 += bias[c2]; v1 += bias[c2+1];
                size_t o = (size_t)(m0+row)*96 + c2;
                float2 xr = *(const float2*)(g_x1 + o);
                float2 w; w.x = xr.x + v0; w.y = xr.y + v1;
                *(float2*)(outf + o) = w;
            }
        }
        __syncthreads();
    }
}

// ---------------- attention core ----------------
// smem: qs | ks | vs bf16 64x104 | at f32 64x68 | pb bf16 64x72 ; st overlays at
__global__ __launch_bounds__(256) void attn_kernel() {
    extern __shared__ char smc[];
    __nv_bfloat16* qs = (__nv_bfloat16*)smc;            // 13312 B each
    __nv_bfloat16* ks = qs + 64*104;
    __nv_bfloat16* vs = ks + 64*104;
    float*         at = (float*)(smc + 3*13312);        // 17408 B
    __nv_bfloat16* pb = (__nv_bfloat16*)(smc + 3*13312 + 17408);  // 9216 B
    float*         st = at;

    const int tid = threadIdx.x, lane = tid & 31, wid = tid >> 5;
    const int win = blockIdx.x, widx = win & 255;
    const size_t rowbase = (size_t)win * 49;

    for (int i = tid; i < 49*36; i += 256) {
        int t = i / 36, p = i % 36;
        uint4 v = *(const uint4*)(g_qkv + (rowbase + t)*288 + p*8);
        __nv_bfloat16* dst = (p < 12) ? (qs + t*104 + p*8)
                           : (p < 24) ? (ks + t*104 + (p-12)*8)
                                      : (vs + t*104 + (p-24)*8);
        *(uint4*)dst = v;
    }
    for (int i = tid; i < 15*13; i += 256) {
        int t = 49 + i/13, p = (i%13)*8;
        uint4 z = make_uint4(0,0,0,0);
        *(uint4*)(qs + t*104 + p) = z;
        *(uint4*)(ks + t*104 + p) = z;
        *(uint4*)(vs + t*104 + p) = z;
    }
    __syncthreads();

    for (int h = 0; h < 3; h++) {
        // logits = Q @ K^T
        {
            int f = wid*2;
            int fr = f >> 2, fc0 = f & 3, fc1 = fc0 + 1;
            wmma::fragment<wmma::accumulator,16,16,16,float> c0, c1;
            wmma::fragment<wmma::matrix_a,16,16,16,__nv_bfloat16,wmma::row_major> a;
            wmma::fragment<wmma::matrix_b,16,16,16,__nv_bfloat16,wmma::col_major> b0, b1;
            wmma::fill_fragment(c0, 0.f); wmma::fill_fragment(c1, 0.f);
            #pragma unroll
            for (int kt = 0; kt < 2; kt++) {
                wmma::load_matrix_sync(a,  qs + (fr*16)*104  + h*32 + kt*16, 104);
                wmma::load_matrix_sync(b0, ks + (fc0*16)*104 + h*32 + kt*16, 104);
                wmma::load_matrix_sync(b1, ks + (fc1*16)*104 + h*32 + kt*16, 104);
                wmma::mma_sync(c0, a, b0, c0);
                wmma::mma_sync(c1, a, b1, c1);
            }
            wmma::store_matrix_sync(at + (fr*16)*68 + fc0*16, c0, 68, wmma::mem_row_major);
            wmma::store_matrix_sync(at + (fr*16)*68 + fc1*16, c1, 68, wmma::mem_row_major);
        }
        __syncthreads();
        // scale + bias/mask + softmax -> bf16 probs
        for (int row = wid; row < 49; row += 8) {
            const float s = 0.17677669529663687f;
            float* p = at + row*68;
            const float* cb = g_comb + (((size_t)widx*3 + h)*49 + row)*49;
            float e0 = p[lane]*s + cb[lane];
            float e1 = (lane < 17) ? p[lane+32]*s + cb[lane+32] : -1e30f;
            float mx = fmaxf(e0, e1);
            #pragma unroll
            for (int o = 16; o; o >>= 1) mx = fmaxf(mx, __shfl_xor_sync(0xffffffffu, mx, o));
            float y0 = __expf(e0 - mx);
            float y1 = (lane < 17) ? __expf(e1 - mx) : 0.f;
            float sum = y0 + y1;
            #pragma unroll
            for (int o = 16; o; o >>= 1) sum += __shfl_xor_sync(0xffffffffu, sum, o);
            float inv = 1.f / sum;
            pb[row*72 + lane]      = __float2bfloat16(y0 * inv);
            pb[row*72 + lane + 32] = __float2bfloat16(y1 * inv);   // zero for lane>=17 (pads 49..63)
        }
        __syncthreads();
        // out = P @ V
        {
            int fr = wid >> 1, fc = wid & 1;
            wmma::fragment<wmma::accumulator,16,16,16,float> c;
            wmma::fragment<wmma::matrix_a,16,16,16,__nv_bfloat16,wmma::row_major> a;
            wmma::fragment<wmma::matrix_b,16,16,16,__nv_bfloat16,wmma::row_major> b;
            wmma::fill_fragment(c, 0.f);
            #pragma unroll
            for (int kt = 0; kt < 4; kt++) {
                wmma::load_matrix_sync(a, pb + (fr*16)*72 + kt*16, 72);
                wmma::load_matrix_sync(b, vs + (kt*16)*104 + h*32 + fc*16, 104);
                wmma::mma_sync(c, a, b, c);
            }
            wmma::store_matrix_sync(st + (fr*16)*36 + fc*16, c, 36, wmma::mem_row_major);
        }
        __syncthreads();
        for (int i = tid; i < 49*16; i += 256) {
            int t = i / 16, d2 = (i % 16) * 2;
            __nv_bfloat162 h2;
            h2.x = __float2bfloat16(st[t*36 + d2]);
            h2.y = __float2bfloat16(st[t*36 + d2 + 1]);
            *(__nv_bfloat162*)(g_att + (rowbase + t)*96 + h*32 + d2) = h2;
        }
        __syncthreads();
    }
}

// ---------------- launch ----------------
extern "C" void kernel_launch(void* const* d_in, const int* in_sizes, int n_in,
                              void* d_out, int out_size) {
    const float* x         = (const float*)d_in[0];
    const float* attn_mask = (const float*)d_in[1];
    const int*   rel_index = (const int*)  d_in[2];
    const float* norm1_g   = (const float*)d_in[3];
    const float* norm1_b   = (const float*)d_in[4];
    const float* qkv_w     = (const float*)d_in[5];
    const float* qkv_b     = (const float*)d_in[6];
    const float* proj_w    = (const float*)d_in[7];
    const float* proj_b    = (const float*)d_in[8];
    const float* rbt       = (const float*)d_in[9];
    const float* norm2_g   = (const float*)d_in[10];
    const float* norm2_b   = (const float*)d_in[11];
    const float* fc1_w     = (const float*)d_in[12];
    const float* fc1_b     = (const float*)d_in[13];
    const float* fc2_w     = (const float*)d_in[14];
    const float* fc2_b     = (const float*)d_in[15];
    float* out = (float*)d_out;

    const int gemm_smem = 29184 + 51200;            // 80384
    const int attn_smem = 3*13312 + 17408 + 9216;   // 66560
    cudaFuncSetAttribute(gemm_kernel<96,3,EPI_QKV>,  cudaFuncAttributeMaxDynamicSharedMemorySize, gemm_smem);
    cudaFuncSetAttribute(gemm_kernel<96,1,EPI_PROJ>, cudaFuncAttributeMaxDynamicSharedMemorySize, gemm_smem);
    cudaFuncSetAttribute(gemm_kernel<96,4,EPI_FC1>,  cudaFuncAttributeMaxDynamicSharedMemorySize, gemm_smem);
    cudaFuncSetAttribute(gemm_kernel<384,1,EPI_FC2>, cudaFuncAttributeMaxDynamicSharedMemorySize, gemm_smem);
    cudaFuncSetAttribute(attn_kernel, cudaFuncAttributeMaxDynamicSharedMemorySize, attn_smem);

    prep_weights<<<(36864 + 255)/256, 256>>>(qkv_w, proj_w, fc1_w, fc2_w);
    prep_comb<<<(256*3*49*49 + 255)/256, 256>>>(attn_mask, rel_index, rbt);
    ln1_gather<<<NWIN, 256>>>(x, norm1_g, norm1_b);
    gemm_kernel<96,3,EPI_QKV><<<MT, 256, gemm_smem>>>(qkv_b, nullptr, nullptr);
    attn_kernel<<<NWIN, 256, attn_smem>>>();
    gemm_kernel<96,1,EPI_PROJ><<<MT, 256, gemm_smem>>>(proj_b, x, nullptr);
    ln2_kernel<<<M_ALL/8, 256>>>(norm2_g, norm2_b);
    gemm_kernel<96,4,EPI_FC1><<<MT, 256, gemm_smem>>>(fc1_b, nullptr, nullptr);
    gemm_kernel<384,1,EPI_FC2><<<MT, 256, gemm_smem>>>(fc2_b, nullptr, out);
}

// round 8
// speedup vs baseline: 3.4636x; 1.0030x over previous
#include <cuda_runtime.h>
#include <cuda_bf16.h>
#include <mma.h>
using namespace nvcuda;

// ---------------- problem constants ----------------
#define LTOT   12544
#define M_ALL  401408
#define NWIN   8192

// ---------------- device scratch ----------------
__device__ __nv_bfloat16 g_wqkv[288*96];
__device__ __nv_bfloat16 g_wproj[96*96];
__device__ __nv_bfloat16 g_wfc1[384*96];
__device__ __nv_bfloat16 g_wfc2[96*384];
__device__ float         g_comb[256*3*49*49];
__device__ float         g_x1[(size_t)M_ALL*96];

// ---------------- prep ----------------
__global__ void prep_weights(const float* __restrict__ qkv_w, const float* __restrict__ proj_w,
                             const float* __restrict__ fc1_w, const float* __restrict__ fc2_w) {
    int i = blockIdx.x * blockDim.x + threadIdx.x;
    if (i < 288*96) g_wqkv[i] = __float2bfloat16(qkv_w[i]);
    if (i < 96*96)  g_wproj[i] = __float2bfloat16(proj_w[i]);
    if (i < 384*96) g_wfc1[i]  = __float2bfloat16(fc1_w[i]);
    if (i < 96*384) g_wfc2[i]  = __float2bfloat16(fc2_w[i]);
}

__global__ void prep_comb(const float* __restrict__ mask, const int* __restrict__ relidx,
                          const float* __restrict__ table) {
    int i = blockIdx.x * blockDim.x + threadIdx.x;
    if (i >= 256*3*49*49) return;
    int m = i % 49; int t = i / 49;
    int r = t % 49; t /= 49;
    int h = t % 3;  int w = t / 3;
    g_comb[i] = table[relidx[r*49 + m]*3 + h] + mask[(w*49 + r)*49 + m];
}

// ---------------- shared GEMM helpers (64x96 tile, 8 warps) ----------------
// warp (wm = wid&3) covers rows wm*16..+16; (wn = wid>>2) covers cols wn*48..+48
template<bool INIT>
__device__ __forceinline__ void gemm64(
    wmma::fragment<wmma::accumulator,16,16,16,float> (&acc)[3],
    const __nv_bfloat16* As, int lda, const __nv_bfloat16* Bs, int wid)
{
    const int wm = wid & 3, wn = wid >> 2;
    if (INIT) {
        #pragma unroll
        for (int ni = 0; ni < 3; ni++) wmma::fill_fragment(acc[ni], 0.f);
    }
    #pragma unroll
    for (int ks = 0; ks < 6; ks++) {
        wmma::fragment<wmma::matrix_a,16,16,16,__nv_bfloat16,wmma::row_major> a;
        wmma::load_matrix_sync(a, As + (wm*16)*lda + ks*16, lda);
        #pragma unroll
        for (int ni = 0; ni < 3; ni++) {
            wmma::fragment<wmma::matrix_b,16,16,16,__nv_bfloat16,wmma::col_major> b;
            wmma::load_matrix_sync(b, Bs + (wn*48 + ni*16)*104 + ks*16, 104);
            wmma::mma_sync(acc[ni], a, b, acc[ni]);
        }
    }
}

__device__ __forceinline__ void store64(
    float* Cs, wmma::fragment<wmma::accumulator,16,16,16,float> (&acc)[3], int wid)
{
    const int wm = wid & 3, wn = wid >> 2;
    #pragma unroll
    for (int ni = 0; ni < 3; ni++)
        wmma::store_matrix_sync(Cs + (wm*16)*100 + wn*48 + ni*16, acc[ni], 100, wmma::mem_row_major);
}

// stage 96x96 weight tile (rows = outputs) into wsm [96][104]; W pre-offset to (row0, col0)
__device__ __forceinline__ void stageB(__nv_bfloat16* wsm, const __nv_bfloat16* W,
                                       int ldw, int tid) {
    for (int i = tid; i < 96*12; i += 256) {
        int n = i/12, k8 = (i%12)*8;
        *(uint4*)(wsm + n*104 + k8) = *(const uint4*)(W + (size_t)n*ldw + k8);
    }
}

// ---------------- fused attention path: LN1 + QKV + attn + proj + residual ----------------
// smem bytes:
//  xs   0      bf16 64x112  (LN'd input; later attention output)
//  qs   14336  bf16 64x104
//  ks   27648  bf16 64x104
//  vs   40960  bf16 64x104
//  wsm  54272  bf16 96x104
//  Cs   74240  f32 64x100  (aliased: at f32 64x68, st f32 64x36)
//  pb   99840  bf16 64x72
//  sidx 109056 int[64]
__global__ __launch_bounds__(256,2) void attn_fused(
    const float* __restrict__ x,
    const float* __restrict__ n1g, const float* __restrict__ n1b,
    const float* __restrict__ qkv_b, const float* __restrict__ proj_b)
{
    extern __shared__ char sm[];
    __nv_bfloat16* xs  = (__nv_bfloat16*)sm;
    __nv_bfloat16* qs  = (__nv_bfloat16*)(sm + 14336);
    __nv_bfloat16* ks_ = (__nv_bfloat16*)(sm + 27648);
    __nv_bfloat16* vs  = (__nv_bfloat16*)(sm + 40960);
    __nv_bfloat16* wsm = (__nv_bfloat16*)(sm + 54272);
    float*         Cs  = (float*)(sm + 74240);
    float*         at  = Cs;
    float*         st  = Cs;
    __nv_bfloat16* pb  = (__nv_bfloat16*)(sm + 99840);
    int*           sidx= (int*)(sm + 109056);

    const int tid = threadIdx.x, lane = tid & 31, wid = tid >> 5;
    const int win = blockIdx.x, b = win >> 8, widx = win & 255;

    if (tid < 49) {
        int rr = tid / 7, cc = tid % 7;
        int hh = ((widx >> 4)*7 + rr + 3) % 112;
        int wp = ((widx & 15)*7 + cc + 3) % 112;
        sidx[tid] = b*LTOT + hh*112 + wp;
    }
    // zero pad rows 49..63 of xs (cols 0..95)
    for (int i = tid; i < 15*12; i += 256) {
        int t = 49 + i/12, k8 = (i%12)*8;
        *(uint4*)(xs + t*112 + k8) = make_uint4(0,0,0,0);
    }
    __syncthreads();

    // LN1 into xs
    for (int t = wid; t < 49; t += 8) {
        const float* xp = x + (size_t)sidx[t]*96;
        float v0 = xp[lane], v1 = xp[lane+32], v2 = xp[lane+64];
        float s = v0+v1+v2, ss = v0*v0 + v1*v1 + v2*v2;
        #pragma unroll
        for (int o = 16; o; o >>= 1) {
            s  += __shfl_xor_sync(0xffffffffu, s,  o);
            ss += __shfl_xor_sync(0xffffffffu, ss, o);
        }
        float mean = s*(1.f/96.f), var = ss*(1.f/96.f) - mean*mean;
        float rstd = rsqrtf(var + 1e-5f);
        xs[t*112+lane]    = __float2bfloat16((v0-mean)*rstd*n1g[lane]    + n1b[lane]);
        xs[t*112+lane+32] = __float2bfloat16((v1-mean)*rstd*n1g[lane+32] + n1b[lane+32]);
        xs[t*112+lane+64] = __float2bfloat16((v2-mean)*rstd*n1g[lane+64] + n1b[lane+64]);
    }
    __syncthreads();

    // QKV GEMM: 64x96 @ (96x96)^T, 3 chunks
    for (int s3 = 0; s3 < 3; s3++) {
        stageB(wsm, g_wqkv + (size_t)s3*96*96, 96, tid);
        __syncthreads();
        wmma::fragment<wmma::accumulator,16,16,16,float> acc[3];
        gemm64<true>(acc, xs, 112, wsm, wid);
        store64(Cs, acc, wid);
        __syncthreads();
        __nv_bfloat16* dst = (s3 == 0) ? qs : (s3 == 1) ? ks_ : vs;
        const float* bptr = qkv_b + s3*96;
        for (int i = tid; i < 64*48; i += 256) {
            int row = i/48, c2 = (i%48)*2;
            __nv_bfloat162 h2;
            h2.x = __float2bfloat16(Cs[row*100+c2]   + bptr[c2]);
            h2.y = __float2bfloat16(Cs[row*100+c2+1] + bptr[c2+1]);
            *(__nv_bfloat162*)(dst + row*104 + c2) = h2;
        }
        __syncthreads();
    }

    // attention per head
    for (int h = 0; h < 3; h++) {
        {   // logits = Q @ K^T
            int f = wid*2;
            int fr = f >> 2, fc0 = f & 3, fc1 = fc0 + 1;
            wmma::fragment<wmma::accumulator,16,16,16,float> c0, c1;
            wmma::fragment<wmma::matrix_a,16,16,16,__nv_bfloat16,wmma::row_major> a;
            wmma::fragment<wmma::matrix_b,16,16,16,__nv_bfloat16,wmma::col_major> b0, b1;
            wmma::fill_fragment(c0, 0.f); wmma::fill_fragment(c1, 0.f);
            #pragma unroll
            for (int kt = 0; kt < 2; kt++) {
                wmma::load_matrix_sync(a,  qs  + (fr*16)*104  + h*32 + kt*16, 104);
                wmma::load_matrix_sync(b0, ks_ + (fc0*16)*104 + h*32 + kt*16, 104);
                wmma::load_matrix_sync(b1, ks_ + (fc1*16)*104 + h*32 + kt*16, 104);
                wmma::mma_sync(c0, a, b0, c0);
                wmma::mma_sync(c1, a, b1, c1);
            }
            wmma::store_matrix_sync(at + (fr*16)*68 + fc0*16, c0, 68, wmma::mem_row_major);
            wmma::store_matrix_sync(at + (fr*16)*68 + fc1*16, c1, 68, wmma::mem_row_major);
        }
        __syncthreads();
        // softmax
        for (int row = wid; row < 49; row += 8) {
            const float s = 0.17677669529663687f;
            float* p = at + row*68;
            const float* cb = g_comb + (((size_t)widx*3 + h)*49 + row)*49;
            float e0 = p[lane]*s + cb[lane];
            float e1 = (lane < 17) ? p[lane+32]*s + cb[lane+32] : -1e30f;
            float mx = fmaxf(e0, e1);
            #pragma unroll
            for (int o = 16; o; o >>= 1) mx = fmaxf(mx, __shfl_xor_sync(0xffffffffu, mx, o));
            float y0 = __expf(e0 - mx);
            float y1 = (lane < 17) ? __expf(e1 - mx) : 0.f;
            float sum = y0 + y1;
            #pragma unroll
            for (int o = 16; o; o >>= 1) sum += __shfl_xor_sync(0xffffffffu, sum, o);
            float inv = 1.f / sum;
            pb[row*72 + lane]      = __float2bfloat16(y0 * inv);
            pb[row*72 + lane + 32] = __float2bfloat16(y1 * inv);  // zero for lane>=17 -> pads 49..63
        }
        __syncthreads();
        {   // out = P @ V
            int fr = wid >> 1, fc = wid & 1;
            wmma::fragment<wmma::accumulator,16,16,16,float> c;
            wmma::fragment<wmma::matrix_a,16,16,16,__nv_bfloat16,wmma::row_major> a;
            wmma::fragment<wmma::matrix_b,16,16,16,__nv_bfloat16,wmma::row_major> bfr;
            wmma::fill_fragment(c, 0.f);
            #pragma unroll
            for (int kt = 0; kt < 4; kt++) {
                wmma::load_matrix_sync(a,   pb + (fr*16)*72 + kt*16, 72);
                wmma::load_matrix_sync(bfr, vs + (kt*16)*104 + h*32 + fc*16, 104);
                wmma::mma_sync(c, a, bfr, c);
            }
            wmma::store_matrix_sync(st + (fr*16)*36 + fc*16, c, 36, wmma::mem_row_major);
        }
        __syncthreads();
        // write head output into xs (xs dead after QKV; pad rows stay zero)
        for (int i = tid; i < 49*16; i += 256) {
            int t = i/16, d2 = (i%16)*2;
            xs[t*112 + h*32 + d2]   = __float2bfloat16(st[t*36 + d2]);
            xs[t*112 + h*32 + d2+1] = __float2bfloat16(st[t*36 + d2 + 1]);
        }
        __syncthreads();
    }

    // proj + residual scatter
    stageB(wsm, g_wproj, 96, tid);
    __syncthreads();
    {
        wmma::fragment<wmma::accumulator,16,16,16,float> acc[3];
        gemm64<true>(acc, xs, 112, wsm, wid);
        store64(Cs, acc, wid);
    }
    __syncthreads();
    for (int i = tid; i < 49*48; i += 256) {
        int row = i/48, c2 = (i%48)*2;
        size_t o = (size_t)sidx[row]*96 + c2;
        float2 xr = *(const float2*)(x + o);
        float2 w;
        w.x = xr.x + Cs[row*100+c2]   + proj_b[c2];
        w.y = xr.y + Cs[row*100+c2+1] + proj_b[c2+1];
        *(float2*)(g_x1 + o) = w;
    }
}

// ---------------- fused MLP: LN2 + fc1 + GELU + fc2 + residual ----------------
// smem: ys 0 (64x112 bf16) | hid 14336 (64x392 bf16) | wsm 64512 (96x104) | Cs 84480 (64x100 f32)
__global__ __launch_bounds__(256,2) void mlp_fused(
    const float* __restrict__ n2g, const float* __restrict__ n2b,
    const float* __restrict__ fc1_b, const float* __restrict__ fc2_b,
    float* __restrict__ out)
{
    extern __shared__ char sm[];
    __nv_bfloat16* ys  = (__nv_bfloat16*)sm;
    __nv_bfloat16* hid = (__nv_bfloat16*)(sm + 14336);
    __nv_bfloat16* wsm = (__nv_bfloat16*)(sm + 64512);
    float*         Cs  = (float*)(sm + 84480);

    const int tid = threadIdx.x, lane = tid & 31, wid = tid >> 5;
    const size_t tok0 = (size_t)blockIdx.x * 64;

    // LN2
    for (int t = wid; t < 64; t += 8) {
        const float* xp = g_x1 + (tok0 + t)*96;
        float v0 = xp[lane], v1 = xp[lane+32], v2 = xp[lane+64];
        float s = v0+v1+v2, ss = v0*v0 + v1*v1 + v2*v2;
        #pragma unroll
        for (int o = 16; o; o >>= 1) {
            s  += __shfl_xor_sync(0xffffffffu, s,  o);
            ss += __shfl_xor_sync(0xffffffffu, ss, o);
        }
        float mean = s*(1.f/96.f), var = ss*(1.f/96.f) - mean*mean;
        float rstd = rsqrtf(var + 1e-5f);
        ys[t*112+lane]    = __float2bfloat16((v0-mean)*rstd*n2g[lane]    + n2b[lane]);
        ys[t*112+lane+32] = __float2bfloat16((v1-mean)*rstd*n2g[lane+32] + n2b[lane+32]);
        ys[t*112+lane+64] = __float2bfloat16((v2-mean)*rstd*n2g[lane+64] + n2b[lane+64]);
    }
    __syncthreads();

    // fc1 + GELU -> hid (never leaves smem)
    for (int nc = 0; nc < 4; nc++) {
        stageB(wsm, g_wfc1 + (size_t)nc*96*96, 96, tid);
        __syncthreads();
        wmma::fragment<wmma::accumulator,16,16,16,float> acc[3];
        gemm64<true>(acc, ys, 112, wsm, wid);
        store64(Cs, acc, wid);
        __syncthreads();
        for (int i = tid; i < 64*48; i += 256) {
            int row = i/48, c2 = (i%48)*2;
            float v0 = Cs[row*100+c2]   + fc1_b[nc*96+c2];
            float v1 = Cs[row*100+c2+1] + fc1_b[nc*96+c2+1];
            v0 = 0.5f*v0*(1.f + erff(v0*0.70710678118654752f));
            v1 = 0.5f*v1*(1.f + erff(v1*0.70710678118654752f));
            __nv_bfloat162 h2;
            h2.x = __float2bfloat16(v0); h2.y = __float2bfloat16(v1);
            *(__nv_bfloat162*)(hid + row*392 + nc*96 + c2) = h2;
        }
        __syncthreads();
    }

    // fc2 (accumulate over 4 k-chunks) + residual
    wmma::fragment<wmma::accumulator,16,16,16,float> acc[3];
    for (int kc = 0; kc < 4; kc++) {
        stageB(wsm, g_wfc2 + kc*96, 384, tid);
        __syncthreads();
        if (kc == 0) gemm64<true >(acc, hid + kc*96, 392, wsm, wid);
        else         gemm64<false>(acc, hid + kc*96, 392, wsm, wid);
        __syncthreads();
    }
    store64(Cs, acc, wid);
    __syncthreads();
    for (int i = tid; i < 64*48; i += 256) {
        int row = i/48, c2 = (i%48)*2;
        size_t o = (tok0 + row)*96 + c2;
        float2 xr = *(const float2*)(g_x1 + o);
        float2 w;
        w.x = xr.x + Cs[row*100+c2]   + fc2_b[c2];
        w.y = xr.y + Cs[row*100+c2+1] + fc2_b[c2+1];
        *(float2*)(out + o) = w;
    }
}

// ---------------- launch ----------------
extern "C" void kernel_launch(void* const* d_in, const int* in_sizes, int n_in,
                              void* d_out, int out_size) {
    const float* x         = (const float*)d_in[0];
    const float* attn_mask = (const float*)d_in[1];
    const int*   rel_index = (const int*)  d_in[2];
    const float* norm1_g   = (const float*)d_in[3];
    const float* norm1_b   = (const float*)d_in[4];
    const float* qkv_w     = (const float*)d_in[5];
    const float* qkv_b     = (const float*)d_in[6];
    const float* proj_w    = (const float*)d_in[7];
    const float* proj_b    = (const float*)d_in[8];
    const float* rbt       = (const float*)d_in[9];
    const float* norm2_g   = (const float*)d_in[10];
    const float* norm2_b   = (const float*)d_in[11];
    const float* fc1_w     = (const float*)d_in[12];
    const float* fc1_b     = (const float*)d_in[13];
    const float* fc2_w     = (const float*)d_in[14];
    const float* fc2_b     = (const float*)d_in[15];
    float* out = (float*)d_out;

    const int attn_smem = 109312;
    const int mlp_smem  = 110080;
    cudaFuncSetAttribute(attn_fused, cudaFuncAttributeMaxDynamicSharedMemorySize, attn_smem);
    cudaFuncSetAttribute(mlp_fused,  cudaFuncAttributeMaxDynamicSharedMemorySize, mlp_smem);

    prep_weights<<<(36864 + 255)/256, 256>>>(qkv_w, proj_w, fc1_w, fc2_w);
    prep_comb<<<(256*3*49*49 + 255)/256, 256>>>(attn_mask, rel_index, rbt);
    attn_fused<<<NWIN, 256, attn_smem>>>(x, norm1_g, norm1_b, qkv_b, proj_b);
    mlp_fused<<<M_ALL/64, 256, mlp_smem>>>(norm2_g, norm2_b, fc1_b, fc2_b, out);
}